// round 4
// baseline (speedup 1.0000x reference)
#include <cuda_runtime.h>

#define BATCH 16384
#define NNZ   819200
#define KDIM  16
#define VOCAB 1000000

__device__ int g_row_ptr[BATCH + 1];
__device__ int g_is64;

// ---------------------------------------------------------------------------
// Detection: interpret buffer as 32-bit words. Words 2i+1 (i < NNZ/2) are
// in-bounds under BOTH dtype views. int64 view: high words == 0. int32 view:
// sorted index values near position NNZ-16 are ~16383 != 0.
// ---------------------------------------------------------------------------
__device__ __forceinline__ int detect_is64(const unsigned int* __restrict__ w) {
    unsigned int acc = 0;
    int base = NNZ / 2 - 8;
#pragma unroll
    for (int i = 0; i < 8; i++) acc |= w[2 * (base + i) + 1];
    return (acc == 0u) ? 1 : 0;
}

// ---------------------------------------------------------------------------
// K1: row_ptr by adjacent difference over the sorted index array.
// Thread i writes row_ptr[r] = i+1 for every boundary r in (idx[i], idx[i+1]].
// One coalesced pass, no binary search. row_ptr[0..idx[0]] = 0 from thread 0.
// ---------------------------------------------------------------------------
template <bool IS64>
__device__ __forceinline__ int load_idx(const void* __restrict__ p, int i) {
    if (IS64) return (int)__ldg((const long long*)p + i);
    return __ldg((const int*)p + i);
}

__global__ void __launch_bounds__(256)
rowptr_kernel(const void* __restrict__ index) {
    __shared__ int s_is64;
    if (threadIdx.x == 0) {
        int is64 = detect_is64((const unsigned int*)index);
        s_is64 = is64;
        if (blockIdx.x == 0) g_is64 = is64;
    }
    __syncthreads();
    const int is64 = s_is64;

    const int i = blockIdx.x * blockDim.x + threadIdx.x;
    if (i >= NNZ) return;

    int a, b;
    if (is64) {
        a = load_idx<true>(index, i);
        b = (i + 1 < NNZ) ? load_idx<true>(index, i + 1) : BATCH;
    } else {
        a = load_idx<false>(index, i);
        b = (i + 1 < NNZ) ? load_idx<false>(index, i + 1) : BATCH;
    }
    if (i == 0)
        for (int r = 0; r <= a; r++) g_row_ptr[r] = 0;
    for (int r = a + 1; r <= b; r++) g_row_ptr[r] = i + 1;
}

// ---------------------------------------------------------------------------
// K2: warp per batch row, chunks of 32 nonzeros. NO mainloop shuffles:
//  - lanes split into 8 groups (g) x 4 slots (m)
//  - first-order: per-lane coalesced (f, v) + one gather instruction
//  - second-order: group-broadcast loads of feats/values (4 lanes share an
//    address -> free broadcast), then float4 embedding loads: one LDG.128
//    retires 8 rows. All front-end loads are independent -> deep MLP.
// ---------------------------------------------------------------------------
__device__ __forceinline__ float warp_sum(float r) {
#pragma unroll
    for (int o = 16; o > 0; o >>= 1)
        r += __shfl_xor_sync(0xffffffffu, r, o);
    return r;
}

template <bool IS64>
__device__ __forceinline__ float fm_row_accum(
        int s, int e, int lane,
        const void* __restrict__ feats,
        const float* __restrict__ values,
        const float* __restrict__ weights,
        const float* __restrict__ embedding) {
    const int g = lane >> 2;   // which nonzero within an octet
    const int m = lane & 3;    // float4 slot: k = 4m .. 4m+3

    float4 t1 = make_float4(0.f, 0.f, 0.f, 0.f);
    float  t2 = 0.f, first = 0.f;

    for (int base = s; base < e; base += 32) {
        // first-order front: coalesced per-lane load + gather
        const int j = base + lane;
        int   f_c = 0;
        float v_c = 0.f;
        if (j < e) { f_c = load_idx<IS64>(feats, j); v_c = __ldg(values + j); }

        // second-order front: group-broadcast (f, v) for this lane's octets
        int   fb[4];
        float vb[4];
#pragma unroll
        for (int t = 0; t < 4; t++) {
            const int jj = base + 8 * t + g;
            if (jj < e) { fb[t] = load_idx<IS64>(feats, jj); vb[t] = __ldg(values + jj); }
            else        { fb[t] = 0;                          vb[t] = 0.f; }
        }

        first += __ldg(weights + f_c) * v_c;

#pragma unroll
        for (int t = 0; t < 4; t++) {
            const float4 ev4 = __ldg((const float4*)(embedding + fb[t] * KDIM) + m);
            const float vv = vb[t];
            const float e0 = ev4.x * vv, e1 = ev4.y * vv,
                        e2 = ev4.z * vv, e3 = ev4.w * vv;
            t1.x += e0; t1.y += e1; t1.z += e2; t1.w += e3;
            t2   += e0 * e0 + e1 * e1 + e2 * e2 + e3 * e3;
        }
    }

    // sum t1 over the 8 groups (group bits = lane bits 2..4)
#pragma unroll
    for (int o = 4; o <= 16; o <<= 1) {
        t1.x += __shfl_xor_sync(0xffffffffu, t1.x, o);
        t1.y += __shfl_xor_sync(0xffffffffu, t1.y, o);
        t1.z += __shfl_xor_sync(0xffffffffu, t1.z, o);
        t1.w += __shfl_xor_sync(0xffffffffu, t1.w, o);
    }

    // 8 lane-replicas per m-slot hold the full t1_k for their 4 ks;
    // 32-lane sum counts each k 8x -> coefficient 0.5/8 = 0.0625.
    float r = 0.0625f * (t1.x * t1.x + t1.y * t1.y + t1.z * t1.z + t1.w * t1.w)
            - 0.5f * t2 + first;
    return warp_sum(r);
}

__global__ void __launch_bounds__(256)
fm_kernel(const void* __restrict__ feats,
          const float* __restrict__ values,
          const float* __restrict__ weights,
          const float* __restrict__ embedding,
          const float* __restrict__ bias,
          float* __restrict__ out) {
    const int warp = (blockIdx.x * blockDim.x + threadIdx.x) >> 5;
    const int lane = threadIdx.x & 31;
    if (warp >= BATCH) return;
    const int b = warp;

    const int s = g_row_ptr[b];
    const int e = g_row_ptr[b + 1];

    float r;
    if (g_is64) r = fm_row_accum<true >(s, e, lane, feats, values, weights, embedding);
    else        r = fm_row_accum<false>(s, e, lane, feats, values, weights, embedding);

    if (lane == 0) {
        const float x = r + __ldg(bias);
        out[b] = 1.0f / (1.0f + expf(-x));
    }
}

// ---------------------------------------------------------------------------
extern "C" void kernel_launch(void* const* d_in, const int* in_sizes, int n_in,
                              void* d_out, int out_size) {
    const void*  index_p   = nullptr;
    const void*  feats_p   = nullptr;
    const float* values_p  = nullptr;
    const float* bias_p    = nullptr;
    const float* weights_p = nullptr;
    const float* embed_p   = nullptr;

    int triple = 0;
    for (int i = 0; i < n_in; i++) {
        int sz = in_sizes[i];
        if (sz == NNZ) {
            if      (triple == 0) index_p  = d_in[i];
            else if (triple == 1) feats_p  = d_in[i];
            else                  values_p = (const float*)d_in[i];
            triple++;
        } else if (sz == VOCAB) {
            weights_p = (const float*)d_in[i];
        } else if (sz == VOCAB * KDIM) {
            embed_p = (const float*)d_in[i];
        } else if (sz == 1) {
            bias_p = (const float*)d_in[i];   // last size-1 input is bias
        }
    }

    float* out = (float*)d_out;
    (void)out_size;

    rowptr_kernel<<<(NNZ + 255) / 256, 256>>>(index_p);
    fm_kernel<<<(BATCH * 32 + 255) / 256, 256>>>(feats_p, values_p, weights_p,
                                                 embed_p, bias_p, out);
}

// round 5
// speedup vs baseline: 1.1807x; 1.1807x over previous
#include <cuda_runtime.h>

#define BATCH 16384
#define NNZ   819200
#define KDIM  16
#define VOCAB 1000000

__device__ int g_row_ptr[BATCH + 1];
__device__ int g_is64;

// ---------------------------------------------------------------------------
// Detection: interpret buffer as 32-bit words. Words 2i+1 (i < NNZ/2) are
// in-bounds under BOTH dtype views. int64 view: high words == 0. int32 view:
// those words are sorted index values ~8191 != 0.
// ---------------------------------------------------------------------------
__device__ __forceinline__ int detect_is64(const unsigned int* __restrict__ w) {
    unsigned int acc = 0;
    int base = NNZ / 2 - 8;
#pragma unroll
    for (int i = 0; i < 8; i++) acc |= w[2 * (base + i) + 1];
    return (acc == 0u) ? 1 : 0;
}

template <bool IS64>
__device__ __forceinline__ int load_idx(const void* __restrict__ p, int i) {
    if (IS64) return (int)__ldg((const long long*)p + i);
    return __ldg((const int*)p + i);
}

// ---------------------------------------------------------------------------
// K1: row_ptr by adjacent difference over the sorted index array.
// Thread i writes row_ptr[r] = i+1 for every boundary r in (idx[i], idx[i+1]].
// One coalesced pass, fully parallel, no binary search.
// ---------------------------------------------------------------------------
__global__ void __launch_bounds__(256)
rowptr_kernel(const void* __restrict__ index) {
    __shared__ int s_is64;
    if (threadIdx.x == 0) {
        int is64 = detect_is64((const unsigned int*)index);
        s_is64 = is64;
        if (blockIdx.x == 0) g_is64 = is64;
    }
    __syncthreads();
    const int is64 = s_is64;

    const int i = blockIdx.x * blockDim.x + threadIdx.x;
    if (i >= NNZ) return;

    int a, b;
    if (is64) {
        a = load_idx<true>(index, i);
        b = (i + 1 < NNZ) ? load_idx<true>(index, i + 1) : BATCH;
    } else {
        a = load_idx<false>(index, i);
        b = (i + 1 < NNZ) ? load_idx<false>(index, i + 1) : BATCH;
    }
    if (i == 0)
        for (int r = 0; r <= a; r++) g_row_ptr[r] = 0;
    for (int r = a + 1; r <= b; r++) g_row_ptr[r] = i + 1;
}

// ---------------------------------------------------------------------------
// K2: warp per batch row, 64-nnz chunks (one chunk covers the average row).
//  - front: 4 independent coalesced loads (f,v for nnz base+lane, base+32+lane)
//  - first-order: 2 gather instructions per 64 nnz
//  - second-order: 8 groups x 4 lanes; per octet t: 2 SHFLs gate one LDG.128
//    that retires 8 embedding rows -> all 8 LDG.128s of a chunk in flight.
//  - butterfly epilogue, no atomics.
// ---------------------------------------------------------------------------
__device__ __forceinline__ float warp_sum(float r) {
#pragma unroll
    for (int o = 16; o > 0; o >>= 1)
        r += __shfl_xor_sync(0xffffffffu, r, o);
    return r;
}

template <bool IS64>
__device__ __forceinline__ float fm_row_accum(
        int s, int e, int lane,
        const void* __restrict__ feats,
        const float* __restrict__ values,
        const float* __restrict__ weights,
        const float* __restrict__ embedding) {
    const int g = lane >> 2;   // octet position 0..7
    const int m = lane & 3;    // float4 slot: k = 4m .. 4m+3

    float4 t1 = make_float4(0.f, 0.f, 0.f, 0.f);
    float  t2 = 0.f, first = 0.f;

    for (int base = s; base < e; base += 64) {
        // front: two 32-coalesced (f, v) loads, clamped + value-predicated
        const int j0 = base + lane;
        const int j1 = j0 + 32;
        const int c0 = (j0 < e) ? j0 : (e - 1);
        const int c1 = (j1 < e) ? j1 : (e - 1);
        const int   f0 = load_idx<IS64>(feats, c0);
        const int   f1 = load_idx<IS64>(feats, c1);
        const float v0 = (j0 < e) ? __ldg(values + j0) : 0.f;
        const float v1 = (j1 < e) ? __ldg(values + j1) : 0.f;

        first += __ldg(weights + f0) * v0;
        first += __ldg(weights + f1) * v1;

        const int fr0 = f0 * KDIM;
        const int fr1 = f1 * KDIM;

#pragma unroll
        for (int t = 0; t < 4; t++) {
            const int src = 8 * t + g;
            {   // nnz = base + 8t + g   (first half)
                const int   fr = __shfl_sync(0xffffffffu, fr0, src);
                const float vv = __shfl_sync(0xffffffffu, v0,  src);
                const float4 ev4 = __ldg((const float4*)(embedding + fr) + m);
                const float e0 = ev4.x * vv, e1 = ev4.y * vv,
                            e2 = ev4.z * vv, e3 = ev4.w * vv;
                t1.x += e0; t1.y += e1; t1.z += e2; t1.w += e3;
                t2   += e0 * e0 + e1 * e1 + e2 * e2 + e3 * e3;
            }
            {   // nnz = base + 32 + 8t + g   (second half)
                const int   fr = __shfl_sync(0xffffffffu, fr1, src);
                const float vv = __shfl_sync(0xffffffffu, v1,  src);
                const float4 ev4 = __ldg((const float4*)(embedding + fr) + m);
                const float e0 = ev4.x * vv, e1 = ev4.y * vv,
                            e2 = ev4.z * vv, e3 = ev4.w * vv;
                t1.x += e0; t1.y += e1; t1.z += e2; t1.w += e3;
                t2   += e0 * e0 + e1 * e1 + e2 * e2 + e3 * e3;
            }
        }
    }

    // sum t1 over the 8 groups (group bits = lane bits 2..4)
#pragma unroll
    for (int o = 4; o <= 16; o <<= 1) {
        t1.x += __shfl_xor_sync(0xffffffffu, t1.x, o);
        t1.y += __shfl_xor_sync(0xffffffffu, t1.y, o);
        t1.z += __shfl_xor_sync(0xffffffffu, t1.z, o);
        t1.w += __shfl_xor_sync(0xffffffffu, t1.w, o);
    }

    // 8 lane-replicas per m-slot hold the full t1_k for their 4 ks;
    // 32-lane sum counts each k 8x -> coefficient 0.5/8 = 0.0625.
    float r = 0.0625f * (t1.x * t1.x + t1.y * t1.y + t1.z * t1.z + t1.w * t1.w)
            - 0.5f * t2 + first;
    return warp_sum(r);
}

__global__ void __launch_bounds__(256)
fm_kernel(const void* __restrict__ feats,
          const float* __restrict__ values,
          const float* __restrict__ weights,
          const float* __restrict__ embedding,
          const float* __restrict__ bias,
          float* __restrict__ out) {
    const int warp = (blockIdx.x * blockDim.x + threadIdx.x) >> 5;
    const int lane = threadIdx.x & 31;
    if (warp >= BATCH) return;
    const int b = warp;

    const int s = g_row_ptr[b];
    const int e = g_row_ptr[b + 1];

    float r = 0.f;
    if (e > s) {
        if (g_is64) r = fm_row_accum<true >(s, e, lane, feats, values, weights, embedding);
        else        r = fm_row_accum<false>(s, e, lane, feats, values, weights, embedding);
    }

    if (lane == 0) {
        const float x = r + __ldg(bias);
        out[b] = 1.0f / (1.0f + expf(-x));
    }
}

// ---------------------------------------------------------------------------
extern "C" void kernel_launch(void* const* d_in, const int* in_sizes, int n_in,
                              void* d_out, int out_size) {
    const void*  index_p   = nullptr;
    const void*  feats_p   = nullptr;
    const float* values_p  = nullptr;
    const float* bias_p    = nullptr;
    const float* weights_p = nullptr;
    const float* embed_p   = nullptr;

    int triple = 0;
    for (int i = 0; i < n_in; i++) {
        int sz = in_sizes[i];
        if (sz == NNZ) {
            if      (triple == 0) index_p  = d_in[i];
            else if (triple == 1) feats_p  = d_in[i];
            else                  values_p = (const float*)d_in[i];
            triple++;
        } else if (sz == VOCAB) {
            weights_p = (const float*)d_in[i];
        } else if (sz == VOCAB * KDIM) {
            embed_p = (const float*)d_in[i];
        } else if (sz == 1) {
            bias_p = (const float*)d_in[i];   // last size-1 input is bias
        }
    }

    float* out = (float*)d_out;
    (void)out_size;

    rowptr_kernel<<<(NNZ + 255) / 256, 256>>>(index_p);
    fm_kernel<<<(BATCH * 32 + 255) / 256, 256>>>(feats_p, values_p, weights_p,
                                                 embed_p, bias_p, out);
}